// round 1
// baseline (speedup 1.0000x reference)
#include <cuda_runtime.h>
#include <cstdint>

#define BB 512
#define HH 1024
#define GG 4096      // 4*H
#define TT 82
#define DD 129
#define STEPS 100
#define XS 2176      // row stride of X: [xt(128) | h0(1024) | h1(1024)]
#define OUTN 128

// ---------------- device scratch (static: allowed) ----------------
__device__ float g_X [BB * XS];        // state: xt | h0 | h1
__device__ float g_C0[BB * HH];        // cell state layer 0
__device__ float g_C1[BB * HH];        // cell state layer 1
__device__ float g_G [BB * GG];        // gate pre-activations
__device__ float g_We0[GG * 1153];     // [enc_Wih0 | enc_Whh0]
__device__ float g_We1[GG * 2048];     // [enc_Wih1 | enc_Whh1]
__device__ float g_Wd0[GG * 1152];     // [dec_Wih0 | dec_Whh0]
__device__ float g_Wd1[GG * 2048];     // [dec_Wih1 | dec_Whh1]
__device__ float g_bias[4 * GG];       // e0, e1, d0, d1  (bih+bhh)
__device__ float g_fcWT[HH * OUTN];    // fc_W transposed: [k][n]

// ---------------- setup kernels ----------------
__global__ void zero_kernel(float* p, int n) {
    for (int i = blockIdx.x * blockDim.x + threadIdx.x; i < n; i += gridDim.x * blockDim.x)
        p[i] = 0.f;
}

// dst[n][k] = k<k1 ? S1[n][k] : S2[n][k-k1],  n in [0,GG)
__global__ void cat2_kernel(float* __restrict__ dst,
                            const float* __restrict__ S1, int k1,
                            const float* __restrict__ S2, int k2) {
    int K = k1 + k2;
    long total = (long)GG * K;
    for (long idx = blockIdx.x * (long)blockDim.x + threadIdx.x; idx < total;
         idx += (long)gridDim.x * blockDim.x) {
        int n = (int)(idx / K);
        int k = (int)(idx % K);
        dst[idx] = (k < k1) ? S1[(size_t)n * k1 + k] : S2[(size_t)n * k2 + (k - k1)];
    }
}

__global__ void transp_fc(const float* __restrict__ fcW) {
    int idx = blockIdx.x * blockDim.x + threadIdx.x;   // HH*OUTN threads
    if (idx >= HH * OUTN) return;
    int k = idx >> 7;          // 0..1023
    int n = idx & 127;         // 0..127
    g_fcWT[idx] = fcW[(size_t)n * HH + k];
}

__global__ void bias_kernel(const float* eb0a, const float* eb0b,
                            const float* eb1a, const float* eb1b,
                            const float* db0a, const float* db0b,
                            const float* db1a, const float* db1b) {
    int n = blockIdx.x * blockDim.x + threadIdx.x;
    if (n >= GG) return;
    g_bias[0 * GG + n] = eb0a[n] + eb0b[n];
    g_bias[1 * GG + n] = eb1a[n] + eb1b[n];
    g_bias[2 * GG + n] = db0a[n] + db0b[n];
    g_bias[3 * GG + n] = db1a[n] + db1b[n];
}

// ---------------- GEMM: C[m][n] = sum_k A(m,k) * W[n][k] + bias[n] ----------------
// A(m,k) = k<K1 ? A1[m*lda1+k] : A2[m*lda2 + (k-K1)]
// M=512 fixed (grid.y=8), N = grid.x*64, C is g_G with ldc=GG.
__global__ __launch_bounds__(128)
void gemm64(const float* __restrict__ A1, int lda1, int K1,
            const float* __restrict__ A2, int lda2,
            const float* __restrict__ W,  int ldw,
            const float* __restrict__ bias,
            float* __restrict__ C, int K) {
    __shared__ float As[16][65];
    __shared__ float Bs[16][65];
    const int tid = threadIdx.x;            // 128 threads
    const int m0 = blockIdx.y * 64;
    const int n0 = blockIdx.x * 64;
    const int tx = tid & 15;                // 16 -> N
    const int ty = tid >> 4;                // 8  -> M
    const int lk = tid & 15;                // k lane for loads
    const int lr = tid >> 4;                // row base for loads

    float acc[8][4];
#pragma unroll
    for (int i = 0; i < 8; i++)
#pragma unroll
        for (int j = 0; j < 4; j++) acc[i][j] = 0.f;

    for (int kt = 0; kt < K; kt += 16) {
        const int gk = kt + lk;
        const bool kok = (gk < K);
#pragma unroll
        for (int p = 0; p < 8; p++) {
            const int r = p * 8 + lr;
            float av = 0.f, bv = 0.f;
            if (kok) {
                const int m = m0 + r;
                av = (gk < K1) ? __ldg(A1 + (size_t)m * lda1 + gk)
                               : __ldg(A2 + (size_t)m * lda2 + (gk - K1));
                bv = __ldg(W + (size_t)(n0 + r) * ldw + gk);
            }
            As[lk][r] = av;
            Bs[lk][r] = bv;
        }
        __syncthreads();
#pragma unroll
        for (int k = 0; k < 16; k++) {
            float a[8], b[4];
#pragma unroll
            for (int i = 0; i < 8; i++) a[i] = As[k][ty * 8 + i];
#pragma unroll
            for (int j = 0; j < 4; j++) b[j] = Bs[k][tx * 4 + j];
#pragma unroll
            for (int i = 0; i < 8; i++)
#pragma unroll
                for (int j = 0; j < 4; j++) acc[i][j] += a[i] * b[j];
        }
        __syncthreads();
    }

#pragma unroll
    for (int i = 0; i < 8; i++) {
        const int m = m0 + ty * 8 + i;
#pragma unroll
        for (int j = 0; j < 4; j++) {
            const int n = n0 + tx * 4 + j;
            C[(size_t)m * GG + n] = acc[i][j] + bias[n];
        }
    }
}

// ---------------- LSTM cell (elementwise) ----------------
// gates order (torch): i, f, g, o in blocks of H
__global__ void lstm_cell(const float* __restrict__ G,
                          float* __restrict__ hbase,      // X + offset, stride XS
                          float* __restrict__ c,          // stride HH
                          const int* __restrict__ lengths,
                          int t, int use_mask,
                          float* __restrict__ hcopy /*unused here, keep null*/) {
    const int idx = blockIdx.x * blockDim.x + threadIdx.x;
    if (idx >= BB * HH) return;
    const int b = idx >> 10;
    const int j = idx & 1023;
    const float* gr = G + (size_t)b * GG;
    const float ig = gr[j];
    const float fg = gr[HH + j];
    const float gg = gr[2 * HH + j];
    const float og = gr[3 * HH + j];
    const float i = 1.f / (1.f + __expf(-ig));
    const float f = 1.f / (1.f + __expf(-fg));
    const float g = tanhf(gg);
    const float o = 1.f / (1.f + __expf(-og));
    float cn = f * c[idx] + i * g;
    float hn = o * tanhf(cn);
    if (use_mask && t >= lengths[b]) {   // packed-seq freeze
        cn = c[idx];
        hn = hbase[(size_t)b * XS + j];
    }
    c[idx] = cn;
    hbase[(size_t)b * XS + j] = hn;
    if (hcopy) hcopy[idx] = hn;
}

// ---------------- fc: out = h1 @ fcW^T + fc_b ; also writes next xt ----------------
// grid = 128 blocks (4 batch rows each), 256 threads: n = tid&127, K-half = tid>>7
__global__ void fc_kernel(const float* __restrict__ fcb,
                          float* __restrict__ out, int t) {
    __shared__ float red[2][4][128];
    const int tid  = threadIdx.x;
    const int n    = tid & 127;
    const int half = tid >> 7;
    const int b0   = blockIdx.x * 4;
    const float* h1p = g_X + (size_t)b0 * XS + 1152;
    float a0 = 0.f, a1 = 0.f, a2 = 0.f, a3 = 0.f;
    const int kb = half * 512;
#pragma unroll 4
    for (int k = kb; k < kb + 512; k++) {
        const float w = g_fcWT[k * OUTN + n];
        a0 += h1p[k] * w;
        a1 += h1p[XS + k] * w;
        a2 += h1p[2 * XS + k] * w;
        a3 += h1p[3 * XS + k] * w;
    }
    red[half][0][n] = a0; red[half][1][n] = a1;
    red[half][2][n] = a2; red[half][3][n] = a3;
    __syncthreads();
    if (half == 0) {
#pragma unroll
        for (int i = 0; i < 4; i++) {
            const float v = red[0][i][n] + red[1][i][n] + fcb[n];
            g_X[(size_t)(b0 + i) * XS + n] = v;                       // next-step xt
            out[((size_t)(b0 + i) * STEPS + t) * OUTN + n] = v;       // output
        }
    }
}

// ---------------- host ----------------
extern "C" void kernel_launch(void* const* d_in, const int* in_sizes, int n_in,
                              void* d_out, int out_size) {
    const float* x      = (const float*)d_in[0];
    const int*   lens   = (const int*)  d_in[1];
    const float* eWih0  = (const float*)d_in[2];
    const float* eWhh0  = (const float*)d_in[3];
    const float* ebih0  = (const float*)d_in[4];
    const float* ebhh0  = (const float*)d_in[5];
    const float* eWih1  = (const float*)d_in[6];
    const float* eWhh1  = (const float*)d_in[7];
    const float* ebih1  = (const float*)d_in[8];
    const float* ebhh1  = (const float*)d_in[9];
    const float* dWih0  = (const float*)d_in[10];
    const float* dWhh0  = (const float*)d_in[11];
    const float* dbih0  = (const float*)d_in[12];
    const float* dbhh0  = (const float*)d_in[13];
    const float* dWih1  = (const float*)d_in[14];
    const float* dWhh1  = (const float*)d_in[15];
    const float* dbih1  = (const float*)d_in[16];
    const float* dbhh1  = (const float*)d_in[17];
    const float* fcW    = (const float*)d_in[18];
    const float* fcb    = (const float*)d_in[19];
    float* out = (float*)d_out;

    float *X, *C0, *C1, *G, *We0, *We1, *Wd0, *Wd1, *Bias;
    cudaGetSymbolAddress((void**)&X,   g_X);
    cudaGetSymbolAddress((void**)&C0,  g_C0);
    cudaGetSymbolAddress((void**)&C1,  g_C1);
    cudaGetSymbolAddress((void**)&G,   g_G);
    cudaGetSymbolAddress((void**)&We0, g_We0);
    cudaGetSymbolAddress((void**)&We1, g_We1);
    cudaGetSymbolAddress((void**)&Wd0, g_Wd0);
    cudaGetSymbolAddress((void**)&Wd1, g_Wd1);
    cudaGetSymbolAddress((void**)&Bias, g_bias);

    // ---- setup (runs every launch; deterministic) ----
    zero_kernel<<<2048, 256>>>(X,  BB * XS);   // also zeroes xt region for dec t=0
    zero_kernel<<<2048, 256>>>(C0, BB * HH);
    zero_kernel<<<2048, 256>>>(C1, BB * HH);
    bias_kernel<<<(GG + 255) / 256, 256>>>(ebih0, ebhh0, ebih1, ebhh1,
                                           dbih0, dbhh0, dbih1, dbhh1);
    cat2_kernel<<<8192, 256>>>(We0, eWih0, DD,   eWhh0, HH);   // 4096x1153
    cat2_kernel<<<8192, 256>>>(We1, eWih1, HH,   eWhh1, HH);   // 4096x2048
    cat2_kernel<<<8192, 256>>>(Wd0, dWih0, OUTN, dWhh0, HH);   // 4096x1152
    cat2_kernel<<<8192, 256>>>(Wd1, dWih1, HH,   dWhh1, HH);   // 4096x2048
    transp_fc<<<(HH * OUTN + 255) / 256, 256>>>(fcW);

    const dim3 gG(64, 8), blk(128);
    const int  ldx = TT * DD;   // 10578

    // ---- encoder: 82 steps ----
    for (int t = 0; t < TT; t++) {
        // layer 0: gates = [x_t | h0] @ We0^T + b_e0
        gemm64<<<gG, blk>>>(x + (size_t)t * DD, ldx, DD,
                            X + 128, XS,
                            We0, 1153, Bias + 0 * GG, G, 1153);
        lstm_cell<<<2048, 256>>>(G, X + 128, C0, lens, t, 1, nullptr);
        // layer 1: gates = [h0 | h1] @ We1^T + b_e1
        gemm64<<<gG, blk>>>(X + 128, XS, 2048,
                            X + 128, XS,
                            We1, 2048, Bias + 1 * GG, G, 2048);
        lstm_cell<<<2048, 256>>>(G, X + 1152, C1, lens, t, 1, nullptr);
    }

    // ---- decoder: 100 steps (xt starts as zeros; fc writes next xt) ----
    for (int t = 0; t < STEPS; t++) {
        // layer 0: gates = [xt | h0] @ Wd0^T + b_d0
        gemm64<<<gG, blk>>>(X, XS, 1152,
                            X, XS,
                            Wd0, 1152, Bias + 2 * GG, G, 1152);
        lstm_cell<<<2048, 256>>>(G, X + 128, C0, lens, t, 0, nullptr);
        // layer 1: gates = [h0 | h1] @ Wd1^T + b_d1
        gemm64<<<gG, blk>>>(X + 128, XS, 2048,
                            X + 128, XS,
                            Wd1, 2048, Bias + 3 * GG, G, 2048);
        lstm_cell<<<2048, 256>>>(G, X + 1152, C1, lens, t, 0, nullptr);
        // fc: out[:, t, :] and next xt
        fc_kernel<<<128, 256>>>(fcb, out, t);
    }
}

// round 3
// speedup vs baseline: 3.5467x; 3.5467x over previous
#include <cuda_runtime.h>
#include <cuda_bf16.h>
#include <cstdint>

#define BB 512
#define HH 1024
#define GG 4096      // 4*H
#define TT 82
#define DD 129
#define STEPS 100
#define XS 2176      // row stride of X / Xb: [xt(128) | h0(1024) | h1(1024)]
#define OUTN 128
#define KE0 1216     // enc L0 K: 1153 padded to 38*32
#define KE1 2048
#define KD0 1152
#define KD1 2048

// ===================== device scratch =====================
__device__ float g_X [BB * XS];          // fp32 state: xt | h0 | h1
__device__ float g_C0[BB * HH];
__device__ float g_C1[BB * HH];
__device__ float g_G [BB * GG];          // gate pre-activations
__device__ __nv_bfloat16 g_Xbh[BB * XS]; // bf16 hi of X
__device__ __nv_bfloat16 g_Xbl[BB * XS]; // bf16 lo of X
__device__ __nv_bfloat16 g_Ah [BB * KE0]; // enc L0 staged A hi
__device__ __nv_bfloat16 g_Al [BB * KE0]; // enc L0 staged A lo
__device__ __nv_bfloat16 g_We0h[GG * KE0];
__device__ __nv_bfloat16 g_We0l[GG * KE0];
__device__ __nv_bfloat16 g_We1h[GG * KE1];
__device__ __nv_bfloat16 g_We1l[GG * KE1];
__device__ __nv_bfloat16 g_Wd0h[GG * KD0];
__device__ __nv_bfloat16 g_Wd0l[GG * KD0];
__device__ __nv_bfloat16 g_Wd1h[GG * KD1];
__device__ __nv_bfloat16 g_Wd1l[GG * KD1];
__device__ float g_bias[4 * GG];
__device__ float g_fcWT[HH * OUTN];

__device__ __forceinline__ void split_bf16(float v, __nv_bfloat16& hi, __nv_bfloat16& lo) {
    hi = __float2bfloat16(v);
    lo = __float2bfloat16(v - __bfloat162float(hi));
}

__device__ __forceinline__ uint32_t smem_u32(const void* p) {
    uint32_t a;
    asm("{ .reg .u64 t; cvta.to.shared.u64 t, %1; cvt.u32.u64 %0, t; }" : "=r"(a) : "l"(p));
    return a;
}
__device__ __forceinline__ void cpa16(uint32_t s, const void* g) {
    asm volatile("cp.async.cg.shared.global [%0], [%1], 16;" :: "r"(s), "l"(g));
}
__device__ __forceinline__ void ldsm4(uint32_t (&d)[4], uint32_t addr) {
    asm volatile("ldmatrix.sync.aligned.m8n8.x4.shared.b16 {%0,%1,%2,%3}, [%4];"
                 : "=r"(d[0]), "=r"(d[1]), "=r"(d[2]), "=r"(d[3]) : "r"(addr));
}
__device__ __forceinline__ void mma16816(float (&d)[4], const uint32_t (&a)[4],
                                         uint32_t b0, uint32_t b1) {
    asm volatile("mma.sync.aligned.m16n8k16.row.col.f32.bf16.bf16.f32 "
                 "{%0,%1,%2,%3},{%4,%5,%6,%7},{%8,%9},{%0,%1,%2,%3};"
                 : "+f"(d[0]), "+f"(d[1]), "+f"(d[2]), "+f"(d[3])
                 : "r"(a[0]), "r"(a[1]), "r"(a[2]), "r"(a[3]), "r"(b0), "r"(b1));
}

// ===================== setup kernels =====================
__global__ void zero_kernel(float* p, int n) {
    for (int i = blockIdx.x * blockDim.x + threadIdx.x; i < n; i += gridDim.x * blockDim.x)
        p[i] = 0.f;
}

// W[n][k] = k<k1 ? S1[n][k] : (k<k1+k2 ? S2[n][k-k1] : 0), split to hi/lo bf16
__global__ void split_cat(__nv_bfloat16* __restrict__ Dh, __nv_bfloat16* __restrict__ Dl,
                          const float* __restrict__ S1, int k1,
                          const float* __restrict__ S2, int k2, int Kp) {
    long total = (long)GG * Kp;
    for (long idx = blockIdx.x * (long)blockDim.x + threadIdx.x; idx < total;
         idx += (long)gridDim.x * blockDim.x) {
        int n = (int)(idx / Kp);
        int k = (int)(idx % Kp);
        float v = 0.f;
        if (k < k1) v = S1[(size_t)n * k1 + k];
        else if (k < k1 + k2) v = S2[(size_t)n * k2 + (k - k1)];
        __nv_bfloat16 hi, lo;
        split_bf16(v, hi, lo);
        Dh[idx] = hi; Dl[idx] = lo;
    }
}

__global__ void transp_fc(const float* __restrict__ fcW) {
    int idx = blockIdx.x * blockDim.x + threadIdx.x;
    if (idx >= HH * OUTN) return;
    int k = idx >> 7, n = idx & 127;
    g_fcWT[idx] = fcW[(size_t)n * HH + k];
}

__global__ void bias_kernel(const float* eb0a, const float* eb0b,
                            const float* eb1a, const float* eb1b,
                            const float* db0a, const float* db0b,
                            const float* db1a, const float* db1b) {
    int n = blockIdx.x * blockDim.x + threadIdx.x;
    if (n >= GG) return;
    g_bias[0 * GG + n] = eb0a[n] + eb0b[n];
    g_bias[1 * GG + n] = eb1a[n] + eb1b[n];
    g_bias[2 * GG + n] = db0a[n] + db0b[n];
    g_bias[3 * GG + n] = db1a[n] + db1b[n];
}

// Stage enc L0 A = [x_t(129) | h0(1024) | pad(63)] as bf16 hi/lo
__global__ void stage_enc(const float* __restrict__ x, int t) {
    int total = BB * KE0;
    for (int idx = blockIdx.x * blockDim.x + threadIdx.x; idx < total;
         idx += gridDim.x * blockDim.x) {
        int b = idx / KE0, k = idx % KE0;
        __nv_bfloat16 hi, lo;
        if (k < DD) {
            split_bf16(x[(size_t)b * (TT * DD) + t * DD + k], hi, lo);
        } else if (k < DD + HH) {
            int j = k - DD;
            hi = g_Xbh[(size_t)b * XS + 128 + j];
            lo = g_Xbl[(size_t)b * XS + 128 + j];
        } else {
            hi = __float2bfloat16(0.f); lo = hi;
        }
        g_Ah[idx] = hi; g_Al[idx] = lo;
    }
}

// ===================== mma.sync GEMM =====================
// C[m][n] = sum_k A(m,k)*W(n,k) + bias[n]; A,W bf16 hi/lo; fp32 accum.
// CTA 128x128, 8 warps (2m x 4n), warp 64x32, K-chunk 32, 2-stage cp.async.
// smem tile: 128 rows x 80B (64B data + 16B pad) per operand.
#define TROW 80
#define TILE_B (128 * TROW)           // 10240
#define STAGE_B (4 * TILE_B)          // 40960
#define SMEM_SZ (2 * STAGE_B)         // 81920

__global__ __launch_bounds__(256, 1)
void gemm_mma(const __nv_bfloat16* __restrict__ Ahi, const __nv_bfloat16* __restrict__ Alo, int lda,
              const __nv_bfloat16* __restrict__ Whi, const __nv_bfloat16* __restrict__ Wlo, int ldw,
              const float* __restrict__ bias, float* __restrict__ C, int K) {
    extern __shared__ char smem[];
    const uint32_t sb = smem_u32(smem);
    const int tid = threadIdx.x;
    const int l = tid & 31;
    const int wid = tid >> 5;
    const int warp_m = wid >> 2;          // 0..1
    const int warp_n = wid & 3;           // 0..3
    const int m0 = blockIdx.y * 128;
    const int n0 = blockIdx.x * 128;

    // ---- loader mapping: thread -> rows (r0, r0+64), 16B column c0 ----
    const int r0 = tid >> 2;
    const int c0 = tid & 3;
    const size_t ldaB = (size_t)lda * 2, ldwB = (size_t)ldw * 2;
    const char* pAh0 = (const char*)Ahi + (size_t)(m0 + r0) * ldaB;
    const char* pAl0 = (const char*)Alo + (size_t)(m0 + r0) * ldaB;
    const char* pWh0 = (const char*)Whi + (size_t)(n0 + r0) * ldwB;
    const char* pWl0 = (const char*)Wlo + (size_t)(n0 + r0) * ldwB;
    const uint32_t srow0 = (uint32_t)r0 * TROW + c0 * 16;
    const uint32_t srow1 = srow0 + 64 * TROW;
    const int nchunks = K >> 5;

    // ---- ldmatrix lane offsets (byte offsets within a tile) ----
    uint32_t aoff[4], boff[2];
#pragma unroll
    for (int wm = 0; wm < 4; wm++)
        aoff[wm] = (uint32_t)(warp_m * 64 + wm * 16 + (l & 15)) * TROW + ((l >> 4) << 4);
#pragma unroll
    for (int p = 0; p < 2; p++)
        boff[p] = (uint32_t)(warp_n * 32 + p * 16 + ((l >> 4) << 3) + (l & 7)) * TROW
                  + (((l >> 3) & 1) << 4);

    float acc[4][4][4];
#pragma unroll
    for (int i = 0; i < 4; i++)
#pragma unroll
        for (int j = 0; j < 4; j++)
#pragma unroll
            for (int q = 0; q < 4; q++) acc[i][j][q] = 0.f;

    // ---- preload chunk 0 -> stage 0 ----
    {
        const int ko = 0 * 64 + c0 * 16;
        const uint32_t s = sb;
        cpa16(s + 0 * TILE_B + srow0, pAh0 + ko);
        cpa16(s + 0 * TILE_B + srow1, pAh0 + 64 * ldaB + ko);
        cpa16(s + 1 * TILE_B + srow0, pAl0 + ko);
        cpa16(s + 1 * TILE_B + srow1, pAl0 + 64 * ldaB + ko);
        cpa16(s + 2 * TILE_B + srow0, pWh0 + ko);
        cpa16(s + 2 * TILE_B + srow1, pWh0 + 64 * ldwB + ko);
        cpa16(s + 3 * TILE_B + srow0, pWl0 + ko);
        cpa16(s + 3 * TILE_B + srow1, pWl0 + 64 * ldwB + ko);
        asm volatile("cp.async.commit_group;");
    }

    for (int kc = 0; kc < nchunks; kc++) {
        if (kc + 1 < nchunks) {
            const int ko = (kc + 1) * 64 + c0 * 16;
            const uint32_t s = sb + ((kc + 1) & 1) * STAGE_B;
            cpa16(s + 0 * TILE_B + srow0, pAh0 + ko);
            cpa16(s + 0 * TILE_B + srow1, pAh0 + 64 * ldaB + ko);
            cpa16(s + 1 * TILE_B + srow0, pAl0 + ko);
            cpa16(s + 1 * TILE_B + srow1, pAl0 + 64 * ldaB + ko);
            cpa16(s + 2 * TILE_B + srow0, pWh0 + ko);
            cpa16(s + 2 * TILE_B + srow1, pWh0 + 64 * ldwB + ko);
            cpa16(s + 3 * TILE_B + srow0, pWl0 + ko);
            cpa16(s + 3 * TILE_B + srow1, pWl0 + 64 * ldwB + ko);
            asm volatile("cp.async.commit_group;");
            asm volatile("cp.async.wait_group 1;");
        } else {
            asm volatile("cp.async.wait_group 0;");
        }
        __syncthreads();

        const uint32_t st = sb + (kc & 1) * STAGE_B;
#pragma unroll
        for (int ks = 0; ks < 2; ks++) {
            const uint32_t kb = (uint32_t)ks * 32;
            uint32_t AH[4][4], AL[4][4], BH[2][4], BL[2][4];
#pragma unroll
            for (int wm = 0; wm < 4; wm++) {
                ldsm4(AH[wm], st + 0 * TILE_B + aoff[wm] + kb);
                ldsm4(AL[wm], st + 1 * TILE_B + aoff[wm] + kb);
            }
#pragma unroll
            for (int p = 0; p < 2; p++) {
                ldsm4(BH[p], st + 2 * TILE_B + boff[p] + kb);
                ldsm4(BL[p], st + 3 * TILE_B + boff[p] + kb);
            }
#pragma unroll
            for (int wm = 0; wm < 4; wm++) {
#pragma unroll
                for (int wn = 0; wn < 4; wn++) {
                    const int p = wn >> 1, h = (wn & 1) << 1;
                    mma16816(acc[wm][wn], AH[wm], BH[p][h], BH[p][h + 1]);
                    mma16816(acc[wm][wn], AH[wm], BL[p][h], BL[p][h + 1]);
                    mma16816(acc[wm][wn], AL[wm], BH[p][h], BH[p][h + 1]);
                }
            }
        }
        __syncthreads();
    }

    // ---- epilogue: bias + store ----
#pragma unroll
    for (int wn = 0; wn < 4; wn++) {
        const int col = n0 + warp_n * 32 + wn * 8 + (l & 3) * 2;
        const float2 bv = *(const float2*)(bias + col);
#pragma unroll
        for (int wm = 0; wm < 4; wm++) {
            const int row = m0 + warp_m * 64 + wm * 16 + (l >> 2);
            float2 v0 = { acc[wm][wn][0] + bv.x, acc[wm][wn][1] + bv.y };
            float2 v1 = { acc[wm][wn][2] + bv.x, acc[wm][wn][3] + bv.y };
            *(float2*)(C + (size_t)row * GG + col) = v0;
            *(float2*)(C + (size_t)(row + 8) * GG + col) = v1;
        }
    }
}

// ===================== LSTM cell =====================
__global__ void lstm_cell(const float* __restrict__ G, int hoff,
                          float* __restrict__ c,
                          const int* __restrict__ lengths,
                          int t, int use_mask) {
    const int idx = blockIdx.x * blockDim.x + threadIdx.x;
    if (idx >= BB * HH) return;
    const int b = idx >> 10;
    const int j = idx & 1023;
    const float* gr = G + (size_t)b * GG;
    const float i = 1.f / (1.f + __expf(-gr[j]));
    const float f = 1.f / (1.f + __expf(-gr[HH + j]));
    const float g = tanhf(gr[2 * HH + j]);
    const float o = 1.f / (1.f + __expf(-gr[3 * HH + j]));
    float cn = f * c[idx] + i * g;
    float hn = o * tanhf(cn);
    const size_t hidx = (size_t)b * XS + hoff + j;
    if (use_mask && t >= lengths[b]) {
        cn = c[idx];
        hn = g_X[hidx];
    }
    c[idx] = cn;
    g_X[hidx] = hn;
    __nv_bfloat16 hi, lo;
    split_bf16(hn, hi, lo);
    g_Xbh[hidx] = hi;
    g_Xbl[hidx] = lo;
}

// ===================== fc =====================
__global__ void fc_kernel(const float* __restrict__ fcb,
                          float* __restrict__ out, int t) {
    __shared__ float red[2][4][128];
    const int tid = threadIdx.x;
    const int n = tid & 127;
    const int half = tid >> 7;
    const int b0 = blockIdx.x * 4;
    const float* h1p = g_X + (size_t)b0 * XS + 1152;
    float a0 = 0.f, a1 = 0.f, a2 = 0.f, a3 = 0.f;
    const int kb = half * 512;
#pragma unroll 4
    for (int k = kb; k < kb + 512; k++) {
        const float w = g_fcWT[k * OUTN + n];
        a0 += h1p[k] * w;
        a1 += h1p[XS + k] * w;
        a2 += h1p[2 * XS + k] * w;
        a3 += h1p[3 * XS + k] * w;
    }
    red[half][0][n] = a0; red[half][1][n] = a1;
    red[half][2][n] = a2; red[half][3][n] = a3;
    __syncthreads();
    if (half == 0) {
#pragma unroll
        for (int i = 0; i < 4; i++) {
            const float v = red[0][i][n] + red[1][i][n] + fcb[n];
            out[((size_t)(b0 + i) * STEPS + t) * OUTN + n] = v;
            __nv_bfloat16 hi, lo;
            split_bf16(v, hi, lo);
            g_Xbh[(size_t)(b0 + i) * XS + n] = hi;
            g_Xbl[(size_t)(b0 + i) * XS + n] = lo;
        }
    }
}

// ===================== host =====================
extern "C" void kernel_launch(void* const* d_in, const int* in_sizes, int n_in,
                              void* d_out, int out_size) {
    const float* x     = (const float*)d_in[0];
    const int*   lens  = (const int*)  d_in[1];
    const float* eWih0 = (const float*)d_in[2];
    const float* eWhh0 = (const float*)d_in[3];
    const float* ebih0 = (const float*)d_in[4];
    const float* ebhh0 = (const float*)d_in[5];
    const float* eWih1 = (const float*)d_in[6];
    const float* eWhh1 = (const float*)d_in[7];
    const float* ebih1 = (const float*)d_in[8];
    const float* ebhh1 = (const float*)d_in[9];
    const float* dWih0 = (const float*)d_in[10];
    const float* dWhh0 = (const float*)d_in[11];
    const float* dbih0 = (const float*)d_in[12];
    const float* dbhh0 = (const float*)d_in[13];
    const float* dWih1 = (const float*)d_in[14];
    const float* dWhh1 = (const float*)d_in[15];
    const float* dbih1 = (const float*)d_in[16];
    const float* dbhh1 = (const float*)d_in[17];
    const float* fcW   = (const float*)d_in[18];
    const float* fcb   = (const float*)d_in[19];
    float* out = (float*)d_out;

    float *X, *C0, *C1, *G, *Bias;
    __nv_bfloat16 *Xbh, *Xbl, *Ah, *Al;
    __nv_bfloat16 *We0h, *We0l, *We1h, *We1l, *Wd0h, *Wd0l, *Wd1h, *Wd1l;
    cudaGetSymbolAddress((void**)&X,    g_X);
    cudaGetSymbolAddress((void**)&C0,   g_C0);
    cudaGetSymbolAddress((void**)&C1,   g_C1);
    cudaGetSymbolAddress((void**)&G,    g_G);
    cudaGetSymbolAddress((void**)&Bias, g_bias);
    cudaGetSymbolAddress((void**)&Xbh,  g_Xbh);
    cudaGetSymbolAddress((void**)&Xbl,  g_Xbl);
    cudaGetSymbolAddress((void**)&Ah,   g_Ah);
    cudaGetSymbolAddress((void**)&Al,   g_Al);
    cudaGetSymbolAddress((void**)&We0h, g_We0h);
    cudaGetSymbolAddress((void**)&We0l, g_We0l);
    cudaGetSymbolAddress((void**)&We1h, g_We1h);
    cudaGetSymbolAddress((void**)&We1l, g_We1l);
    cudaGetSymbolAddress((void**)&Wd0h, g_Wd0h);
    cudaGetSymbolAddress((void**)&Wd0l, g_Wd0l);
    cudaGetSymbolAddress((void**)&Wd1h, g_Wd1h);
    cudaGetSymbolAddress((void**)&Wd1l, g_Wd1l);

    cudaFuncSetAttribute(gemm_mma, cudaFuncAttributeMaxDynamicSharedMemorySize, SMEM_SZ);

    // ---- setup ----
    zero_kernel<<<2048, 256>>>(X,  BB * XS);
    zero_kernel<<<2048, 256>>>(C0, BB * HH);
    zero_kernel<<<2048, 256>>>(C1, BB * HH);
    zero_kernel<<<2048, 256>>>((float*)Xbh, BB * XS / 2);
    zero_kernel<<<2048, 256>>>((float*)Xbl, BB * XS / 2);
    bias_kernel<<<(GG + 255) / 256, 256>>>(ebih0, ebhh0, ebih1, ebhh1,
                                           dbih0, dbhh0, dbih1, dbhh1);
    split_cat<<<4096, 256>>>(We0h, We0l, eWih0, DD,   eWhh0, HH, KE0);
    split_cat<<<4096, 256>>>(We1h, We1l, eWih1, HH,   eWhh1, HH, KE1);
    split_cat<<<4096, 256>>>(Wd0h, Wd0l, dWih0, OUTN, dWhh0, HH, KD0);
    split_cat<<<4096, 256>>>(Wd1h, Wd1l, dWih1, HH,   dWhh1, HH, KD1);
    transp_fc<<<(HH * OUTN + 255) / 256, 256>>>(fcW);

    const dim3 gg(32, 4), gb(256);

    // ---- encoder: 82 steps ----
    for (int t = 0; t < TT; t++) {
        stage_enc<<<1216, 256>>>(x, t);
        gemm_mma<<<gg, gb, SMEM_SZ>>>(Ah, Al, KE0, We0h, We0l, KE0,
                                      Bias + 0 * GG, G, KE0);
        lstm_cell<<<2048, 256>>>(G, 128, C0, lens, t, 1);
        gemm_mma<<<gg, gb, SMEM_SZ>>>(Xbh + 128, Xbl + 128, XS, We1h, We1l, KE1,
                                      Bias + 1 * GG, G, KE1);
        lstm_cell<<<2048, 256>>>(G, 1152, C1, lens, t, 1);
    }

    // ---- decoder: 100 steps ----
    for (int t = 0; t < STEPS; t++) {
        gemm_mma<<<gg, gb, SMEM_SZ>>>(Xbh, Xbl, XS, Wd0h, Wd0l, KD0,
                                      Bias + 2 * GG, G, KD0);
        lstm_cell<<<2048, 256>>>(G, 128, C0, lens, t, 0);
        gemm_mma<<<gg, gb, SMEM_SZ>>>(Xbh + 128, Xbl + 128, XS, Wd1h, Wd1l, KD1,
                                      Bias + 3 * GG, G, KD1);
        lstm_cell<<<2048, 256>>>(G, 1152, C1, lens, t, 0);
        fc_kernel<<<128, 256>>>(fcb, out, t);
    }
}

// round 4
// speedup vs baseline: 4.0193x; 1.1333x over previous
#include <cuda_runtime.h>
#include <cuda_bf16.h>
#include <cstdint>

#define BB 512
#define HH 1024
#define GG 4096      // 4*H
#define TT 82
#define DD 129
#define STEPS 100
#define XS 2176      // row stride of X / Xb: [xt(128) | h0(1024) | h1(1024)]
#define OUTN 128
#define KE0 1216     // enc L0 K: 1153 padded to 19*64
#define KE1 2048
#define KD0 1152
#define KD1 2048

// ===================== device scratch =====================
__device__ float g_X [BB * XS];          // fp32 state: xt | h0 | h1
__device__ float g_C0[BB * HH];
__device__ float g_C1[BB * HH];
__device__ __nv_bfloat16 g_Xbh[BB * XS]; // bf16 hi of X
__device__ __nv_bfloat16 g_Xbl[BB * XS]; // bf16 lo of X
__device__ __nv_bfloat16 g_Ah [BB * KE0]; // enc L0 staged A hi: [x_t | h0 | pad]
__device__ __nv_bfloat16 g_Al [BB * KE0];
__device__ __nv_bfloat16 g_We0h[GG * KE0];   // gate-interleaved rows: n' = 4*ch + gate
__device__ __nv_bfloat16 g_We0l[GG * KE0];
__device__ __nv_bfloat16 g_We1h[GG * KE1];
__device__ __nv_bfloat16 g_We1l[GG * KE1];
__device__ __nv_bfloat16 g_Wd0h[GG * KD0];
__device__ __nv_bfloat16 g_Wd0l[GG * KD0];
__device__ __nv_bfloat16 g_Wd1h[GG * KD1];
__device__ __nv_bfloat16 g_Wd1l[GG * KD1];
__device__ float g_bias[4 * GG];         // gate-interleaved
__device__ float g_fcWT[HH * OUTN];

__device__ __forceinline__ void split_bf16(float v, __nv_bfloat16& hi, __nv_bfloat16& lo) {
    hi = __float2bfloat16(v);
    lo = __float2bfloat16(v - __bfloat162float(hi));
}
__device__ __forceinline__ uint32_t smem_u32(const void* p) {
    uint32_t a;
    asm("{ .reg .u64 t; cvta.to.shared.u64 t, %1; cvt.u32.u64 %0, t; }" : "=r"(a) : "l"(p));
    return a;
}
__device__ __forceinline__ void cpa16(uint32_t s, const void* g) {
    asm volatile("cp.async.cg.shared.global [%0], [%1], 16;" :: "r"(s), "l"(g));
}
__device__ __forceinline__ void ldsm4(uint32_t (&d)[4], uint32_t addr) {
    asm volatile("ldmatrix.sync.aligned.m8n8.x4.shared.b16 {%0,%1,%2,%3}, [%4];"
                 : "=r"(d[0]), "=r"(d[1]), "=r"(d[2]), "=r"(d[3]) : "r"(addr));
}
__device__ __forceinline__ void mma16816(float (&d)[4], const uint32_t (&a)[4],
                                         uint32_t b0, uint32_t b1) {
    asm volatile("mma.sync.aligned.m16n8k16.row.col.f32.bf16.bf16.f32 "
                 "{%0,%1,%2,%3},{%4,%5,%6,%7},{%8,%9},{%0,%1,%2,%3};"
                 : "+f"(d[0]), "+f"(d[1]), "+f"(d[2]), "+f"(d[3])
                 : "r"(a[0]), "r"(a[1]), "r"(a[2]), "r"(a[3]), "r"(b0), "r"(b1));
}

// ===================== setup kernels =====================
__global__ void zero_kernel(float* p, int n) {
    for (int i = blockIdx.x * blockDim.x + threadIdx.x; i < n; i += gridDim.x * blockDim.x)
        p[i] = 0.f;
}

// Gate-interleaved: dest row nd = 4*ch + gate; source row = gate*1024 + ch.
// dst[nd][k] = k<k1 ? S1[src][k] : (k<k1+k2 ? S2[src][k-k1] : 0), split to hi/lo bf16
__global__ void split_cat(__nv_bfloat16* __restrict__ Dh, __nv_bfloat16* __restrict__ Dl,
                          const float* __restrict__ S1, int k1,
                          const float* __restrict__ S2, int k2, int Kp) {
    long total = (long)GG * Kp;
    for (long idx = blockIdx.x * (long)blockDim.x + threadIdx.x; idx < total;
         idx += (long)gridDim.x * blockDim.x) {
        int nd = (int)(idx / Kp);
        int k  = (int)(idx % Kp);
        int ch = nd >> 2, gate = nd & 3;
        int n = gate * HH + ch;
        float v = 0.f;
        if (k < k1) v = S1[(size_t)n * k1 + k];
        else if (k < k1 + k2) v = S2[(size_t)n * k2 + (k - k1)];
        __nv_bfloat16 hi, lo;
        split_bf16(v, hi, lo);
        Dh[idx] = hi; Dl[idx] = lo;
    }
}

__global__ void transp_fc(const float* __restrict__ fcW) {
    int idx = blockIdx.x * blockDim.x + threadIdx.x;
    if (idx >= HH * OUTN) return;
    int k = idx >> 7, n = idx & 127;
    g_fcWT[idx] = fcW[(size_t)n * HH + k];
}

__global__ void bias_kernel(const float* eb0a, const float* eb0b,
                            const float* eb1a, const float* eb1b,
                            const float* db0a, const float* db0b,
                            const float* db1a, const float* db1b) {
    int nd = blockIdx.x * blockDim.x + threadIdx.x;
    if (nd >= GG) return;
    int ch = nd >> 2, gate = nd & 3;
    int n = gate * HH + ch;
    g_bias[0 * GG + nd] = eb0a[n] + eb0b[n];
    g_bias[1 * GG + nd] = eb1a[n] + eb1b[n];
    g_bias[2 * GG + nd] = db0a[n] + db0b[n];
    g_bias[3 * GG + nd] = db1a[n] + db1b[n];
}

// copy x_t (512 x 129) into staged enc A buffer (bf16 hi/lo)
__global__ void stage_x(const float* __restrict__ x, int t) {
    int idx = blockIdx.x * blockDim.x + threadIdx.x;
    if (idx >= BB * DD) return;
    int b = idx / DD, k = idx % DD;
    __nv_bfloat16 hi, lo;
    split_bf16(x[(size_t)b * (TT * DD) + t * DD + k], hi, lo);
    g_Ah[(size_t)b * KE0 + k] = hi;
    g_Al[(size_t)b * KE0 + k] = lo;
}

// ===================== fused GEMM + LSTM cell =====================
// gates[m][nd] = sum_k A(m,k)*W(nd,k) + bias[nd], nd = 4*ch+gate (interleaved).
// Then cell applied in epilogue. CTA 128x128, 8 warps (2m x 4n), K-chunk 64,
// 3-stage cp.async pipeline, XOR-swizzled smem (128B rows).
#define TBYTES 16384                 // 128 rows x 128B
#define STAGE_B (4 * TBYTES)         // 65536
#define SMEM_SZ (3 * STAGE_B)        // 196608

__global__ __launch_bounds__(256, 1)
void gemm_cell(const __nv_bfloat16* __restrict__ Ahi, const __nv_bfloat16* __restrict__ Alo, int lda,
               const __nv_bfloat16* __restrict__ Whi, const __nv_bfloat16* __restrict__ Wlo, int ldw,
               const float* __restrict__ bias,
               float* __restrict__ Cc,            // cell state [BB][HH]
               const int* __restrict__ lengths, int t, int use_mask, int hoff,
               __nv_bfloat16* __restrict__ sAh,   // optional staging (enc L0 h0), else null
               __nv_bfloat16* __restrict__ sAl,
               int K) {
    extern __shared__ char smem[];
    const uint32_t sb = smem_u32(smem);
    const int tid = threadIdx.x;
    const int l = tid & 31;
    const int wid = tid >> 5;
    const int warp_m = wid >> 2;          // 0..1
    const int warp_n = wid & 3;           // 0..3
    const int m0 = blockIdx.y * 128;
    const int n0 = blockIdx.x * 128;

    // ---- loader mapping: thread -> (rowL + 32*it, col16), XOR swizzle ----
    const int rowL = tid >> 3;            // 0..31
    const int colL = tid & 7;             // 16B column
    const uint32_t swL = (uint32_t)(colL ^ (rowL & 7)) * 16;
    const size_t ldaB = (size_t)lda * 2, ldwB = (size_t)ldw * 2;
    const char* pAh = (const char*)Ahi + (size_t)(m0 + rowL) * ldaB + colL * 16;
    const char* pAl = (const char*)Alo + (size_t)(m0 + rowL) * ldaB + colL * 16;
    const char* pWh = (const char*)Whi + (size_t)(n0 + rowL) * ldwB + colL * 16;
    const char* pWl = (const char*)Wlo + (size_t)(n0 + rowL) * ldwB + colL * 16;
    const int nchunks = K >> 6;

#define LOADCHUNK(s, kc) do {                                                      \
    const uint32_t st_ = sb + (s) * STAGE_B;                                       \
    const size_t ko_ = (size_t)(kc) * 128;                                         \
    _Pragma("unroll")                                                              \
    for (int it = 0; it < 4; it++) {                                               \
        const uint32_t so_ = (uint32_t)(rowL + 32 * it) * 128 + swL;               \
        cpa16(st_ + 0 * TBYTES + so_, pAh + ko_ + (size_t)(32 * it) * ldaB);       \
        cpa16(st_ + 1 * TBYTES + so_, pAl + ko_ + (size_t)(32 * it) * ldaB);       \
        cpa16(st_ + 2 * TBYTES + so_, pWh + ko_ + (size_t)(32 * it) * ldwB);       \
        cpa16(st_ + 3 * TBYTES + so_, pWl + ko_ + (size_t)(32 * it) * ldwB);       \
    }                                                                              \
    asm volatile("cp.async.commit_group;");                                        \
} while (0)

    // ---- ldmatrix lane bases ----
    uint32_t arow[4], ar7[4];
#pragma unroll
    for (int wm = 0; wm < 4; wm++) {
        const uint32_t r = warp_m * 64 + wm * 16 + (l & 15);
        arow[wm] = r * 128;
        ar7[wm]  = r & 7;
    }
    uint32_t brow[2], br7[2];
#pragma unroll
    for (int p = 0; p < 2; p++) {
        const uint32_t r = warp_n * 32 + p * 16 + ((l >> 4) << 3) + (l & 7);
        brow[p] = r * 128;
        br7[p]  = r & 7;
    }
    const uint32_t acsel = (uint32_t)(l >> 4);       // A: k8 half select
    const uint32_t bcsel = (uint32_t)((l >> 3) & 1); // B: k8 half select

    float acc[4][4][4];
#pragma unroll
    for (int i = 0; i < 4; i++)
#pragma unroll
        for (int j = 0; j < 4; j++)
#pragma unroll
            for (int q = 0; q < 4; q++) acc[i][j][q] = 0.f;

    // ---- preload chunks 0,1 ----
    LOADCHUNK(0, 0);
    LOADCHUNK(1, 1);

    for (int kc = 0; kc < nchunks; kc++) {
        if (kc + 2 < nchunks) {
            asm volatile("cp.async.wait_group 1;");
        } else {
            asm volatile("cp.async.wait_group 0;");
        }
        __syncthreads();
        if (kc + 2 < nchunks) {
            const int s = (kc + 2) % 3;
            LOADCHUNK(s, kc + 2);
        }
        const uint32_t st = sb + (kc % 3) * STAGE_B;
#pragma unroll
        for (int ks = 0; ks < 4; ks++) {
            uint32_t AH[4][4], AL[4][4], BH[2][4], BL[2][4];
#pragma unroll
            for (int wm = 0; wm < 4; wm++) {
                const uint32_t c = (uint32_t)(2 * ks) + acsel;
                const uint32_t off = arow[wm] + ((c ^ ar7[wm]) << 4);
                ldsm4(AH[wm], st + 0 * TBYTES + off);
                ldsm4(AL[wm], st + 1 * TBYTES + off);
            }
#pragma unroll
            for (int p = 0; p < 2; p++) {
                const uint32_t c = (uint32_t)(2 * ks) + bcsel;
                const uint32_t off = brow[p] + ((c ^ br7[p]) << 4);
                ldsm4(BH[p], st + 2 * TBYTES + off);
                ldsm4(BL[p], st + 3 * TBYTES + off);
            }
#pragma unroll
            for (int wm = 0; wm < 4; wm++) {
#pragma unroll
                for (int wn = 0; wn < 4; wn++) {
                    const int p = wn >> 1, h = (wn & 1) << 1;
                    mma16816(acc[wm][wn], AH[wm], BH[p][h], BH[p][h + 1]);
                    mma16816(acc[wm][wn], AH[wm], BL[p][h], BL[p][h + 1]);
                    mma16816(acc[wm][wn], AL[wm], BH[p][h], BH[p][h + 1]);
                }
            }
        }
        __syncthreads();
    }

    // ---- epilogue: acc + bias -> smem (row stride 132 floats) ----
    float* cs = (float*)smem;
#pragma unroll
    for (int wn = 0; wn < 4; wn++) {
        const int cl = warp_n * 32 + wn * 8 + (l & 3) * 2;
        const float2 bv = *(const float2*)(bias + n0 + cl);
#pragma unroll
        for (int wm = 0; wm < 4; wm++) {
            const int rl = warp_m * 64 + wm * 16 + (l >> 2);
            cs[rl * 132 + cl]           = acc[wm][wn][0] + bv.x;
            cs[rl * 132 + cl + 1]       = acc[wm][wn][1] + bv.y;
            cs[(rl + 8) * 132 + cl]     = acc[wm][wn][2] + bv.x;
            cs[(rl + 8) * 132 + cl + 1] = acc[wm][wn][3] + bv.y;
        }
    }
    __syncthreads();

    // ---- LSTM cell: 128 batch x 32 channels, 16 per thread ----
    const int ch0 = n0 >> 2;
#pragma unroll
    for (int it = 0; it < 16; it++) {
        const int idx = it * 256 + tid;
        const int bl = idx >> 5;
        const int jl = idx & 31;
        const float4 v = *(const float4*)&cs[bl * 132 + 4 * jl];
        const int b = m0 + bl;
        const int j = ch0 + jl;
        const float ig = 1.f / (1.f + __expf(-v.x));
        const float fg = 1.f / (1.f + __expf(-v.y));
        const float gg = tanhf(v.z);
        const float og = 1.f / (1.f + __expf(-v.w));
        const size_t cidx = (size_t)b * HH + j;
        const size_t hidx = (size_t)b * XS + hoff + j;
        const float cold = Cc[cidx];
        float cn = fg * cold + ig * gg;
        float hn = og * tanhf(cn);
        if (use_mask && t >= lengths[b]) {
            cn = cold;
            hn = g_X[hidx];
        }
        Cc[cidx] = cn;
        g_X[hidx] = hn;
        __nv_bfloat16 hi, lo;
        split_bf16(hn, hi, lo);
        g_Xbh[hidx] = hi;
        g_Xbl[hidx] = lo;
        if (sAh) {
            const size_t aidx = (size_t)b * KE0 + DD + j;
            sAh[aidx] = hi;
            sAl[aidx] = lo;
        }
    }
}

// ===================== fc: out = h1 @ fcW^T + b; writes next xt (bf16 split) =====================
__global__ void fc_kernel(const float* __restrict__ fcb,
                          float* __restrict__ out, int t) {
    __shared__ float red[2][4][128];
    const int tid = threadIdx.x;
    const int n = tid & 127;
    const int half = tid >> 7;
    const int b0 = blockIdx.x * 4;
    const float* h1p = g_X + (size_t)b0 * XS + 1152;
    float a0 = 0.f, a1 = 0.f, a2 = 0.f, a3 = 0.f;
    const int kb = half * 512;
#pragma unroll 4
    for (int k = kb; k < kb + 512; k++) {
        const float w = g_fcWT[k * OUTN + n];
        a0 += h1p[k] * w;
        a1 += h1p[XS + k] * w;
        a2 += h1p[2 * XS + k] * w;
        a3 += h1p[3 * XS + k] * w;
    }
    red[half][0][n] = a0; red[half][1][n] = a1;
    red[half][2][n] = a2; red[half][3][n] = a3;
    __syncthreads();
    if (half == 0) {
#pragma unroll
        for (int i = 0; i < 4; i++) {
            const float v = red[0][i][n] + red[1][i][n] + fcb[n];
            out[((size_t)(b0 + i) * STEPS + t) * OUTN + n] = v;
            __nv_bfloat16 hi, lo;
            split_bf16(v, hi, lo);
            g_Xbh[(size_t)(b0 + i) * XS + n] = hi;
            g_Xbl[(size_t)(b0 + i) * XS + n] = lo;
        }
    }
}

// ===================== host =====================
extern "C" void kernel_launch(void* const* d_in, const int* in_sizes, int n_in,
                              void* d_out, int out_size) {
    const float* x     = (const float*)d_in[0];
    const int*   lens  = (const int*)  d_in[1];
    const float* eWih0 = (const float*)d_in[2];
    const float* eWhh0 = (const float*)d_in[3];
    const float* ebih0 = (const float*)d_in[4];
    const float* ebhh0 = (const float*)d_in[5];
    const float* eWih1 = (const float*)d_in[6];
    const float* eWhh1 = (const float*)d_in[7];
    const float* ebih1 = (const float*)d_in[8];
    const float* ebhh1 = (const float*)d_in[9];
    const float* dWih0 = (const float*)d_in[10];
    const float* dWhh0 = (const float*)d_in[11];
    const float* dbih0 = (const float*)d_in[12];
    const float* dbhh0 = (const float*)d_in[13];
    const float* dWih1 = (const float*)d_in[14];
    const float* dWhh1 = (const float*)d_in[15];
    const float* dbih1 = (const float*)d_in[16];
    const float* dbhh1 = (const float*)d_in[17];
    const float* fcW   = (const float*)d_in[18];
    const float* fcb   = (const float*)d_in[19];
    float* out = (float*)d_out;

    float *X, *C0, *C1, *Bias;
    __nv_bfloat16 *Xbh, *Xbl, *Ah, *Al;
    __nv_bfloat16 *We0h, *We0l, *We1h, *We1l, *Wd0h, *Wd0l, *Wd1h, *Wd1l;
    cudaGetSymbolAddress((void**)&X,    g_X);
    cudaGetSymbolAddress((void**)&C0,   g_C0);
    cudaGetSymbolAddress((void**)&C1,   g_C1);
    cudaGetSymbolAddress((void**)&Bias, g_bias);
    cudaGetSymbolAddress((void**)&Xbh,  g_Xbh);
    cudaGetSymbolAddress((void**)&Xbl,  g_Xbl);
    cudaGetSymbolAddress((void**)&Ah,   g_Ah);
    cudaGetSymbolAddress((void**)&Al,   g_Al);
    cudaGetSymbolAddress((void**)&We0h, g_We0h);
    cudaGetSymbolAddress((void**)&We0l, g_We0l);
    cudaGetSymbolAddress((void**)&We1h, g_We1h);
    cudaGetSymbolAddress((void**)&We1l, g_We1l);
    cudaGetSymbolAddress((void**)&Wd0h, g_Wd0h);
    cudaGetSymbolAddress((void**)&Wd0l, g_Wd0l);
    cudaGetSymbolAddress((void**)&Wd1h, g_Wd1h);
    cudaGetSymbolAddress((void**)&Wd1l, g_Wd1l);

    cudaFuncSetAttribute(gemm_cell, cudaFuncAttributeMaxDynamicSharedMemorySize, SMEM_SZ);

    // ---- setup ----
    zero_kernel<<<2048, 256>>>(X,  BB * XS);
    zero_kernel<<<2048, 256>>>(C0, BB * HH);
    zero_kernel<<<2048, 256>>>(C1, BB * HH);
    zero_kernel<<<2048, 256>>>((float*)Xbh, BB * XS / 2);
    zero_kernel<<<2048, 256>>>((float*)Xbl, BB * XS / 2);
    zero_kernel<<<2048, 256>>>((float*)Ah,  BB * KE0 / 2);
    zero_kernel<<<2048, 256>>>((float*)Al,  BB * KE0 / 2);
    bias_kernel<<<(GG + 255) / 256, 256>>>(ebih0, ebhh0, ebih1, ebhh1,
                                           dbih0, dbhh0, dbih1, dbhh1);
    split_cat<<<4096, 256>>>(We0h, We0l, eWih0, DD,   eWhh0, HH, KE0);
    split_cat<<<4096, 256>>>(We1h, We1l, eWih1, HH,   eWhh1, HH, KE1);
    split_cat<<<4096, 256>>>(Wd0h, Wd0l, dWih0, OUTN, dWhh0, HH, KD0);
    split_cat<<<4096, 256>>>(Wd1h, Wd1l, dWih1, HH,   dWhh1, HH, KD1);
    transp_fc<<<(HH * OUTN + 255) / 256, 256>>>(fcW);

    const dim3 gg(32, 4), gb(256);

    // ---- encoder: 82 steps ----
    for (int t = 0; t < TT; t++) {
        stage_x<<<(BB * DD + 255) / 256, 256>>>(x, t);
        gemm_cell<<<gg, gb, SMEM_SZ>>>(Ah, Al, KE0, We0h, We0l, KE0,
                                       Bias + 0 * GG, C0, lens, t, 1, 128,
                                       Ah, Al, KE0);
        gemm_cell<<<gg, gb, SMEM_SZ>>>(Xbh + 128, Xbl + 128, XS, We1h, We1l, KE1,
                                       Bias + 1 * GG, C1, lens, t, 1, 1152,
                                       nullptr, nullptr, KE1);
    }

    // ---- decoder: 100 steps ----
    for (int t = 0; t < STEPS; t++) {
        gemm_cell<<<gg, gb, SMEM_SZ>>>(Xbh, Xbl, XS, Wd0h, Wd0l, KD0,
                                       Bias + 2 * GG, C0, lens, t, 0, 128,
                                       nullptr, nullptr, KD0);
        gemm_cell<<<gg, gb, SMEM_SZ>>>(Xbh + 128, Xbl + 128, XS, Wd1h, Wd1l, KD1,
                                       Bias + 3 * GG, C1, lens, t, 0, 1152,
                                       nullptr, nullptr, KD1);
        fc_kernel<<<128, 256>>>(fcb, out, t);
    }
}

// round 5
// speedup vs baseline: 8.2534x; 2.0534x over previous
#include <cuda_runtime.h>
#include <cuda_fp16.h>
#include <cstdint>

#define BB 512
#define HH 1024
#define GG 4096      // 4*H
#define TT 82
#define DD 129
#define STEPS 100
#define XS 2176      // row stride of X / Xh: [xt(128) | h0(1024) | h1(1024)]
#define OUTN 128
#define KE0 1216     // enc L0 K: 1153 padded to 19*64
#define KE1 2048
#define KD0 1152
#define KD1 2048

// ===================== device scratch =====================
__device__ float g_X [BB * XS];          // fp32 state: xt | h0 | h1
__device__ float g_C0[BB * HH];
__device__ float g_C1[BB * HH];
__device__ __half g_Xh[BB * XS];         // fp16 mirror of X (GEMM A operand)
__device__ __half g_A [BB * KE0];        // enc L0 staged A: [x_t | h0 | pad]
__device__ __half g_We0[GG * KE0];       // gate-interleaved rows: n' = 4*ch + gate
__device__ __half g_We1[GG * KE1];
__device__ __half g_Wd0[GG * KD0];
__device__ __half g_Wd1[GG * KD1];
__device__ float g_bias[4 * GG];         // gate-interleaved
__device__ float g_fcWT[HH * OUTN];

__device__ __forceinline__ uint32_t smem_u32(const void* p) {
    uint32_t a;
    asm("{ .reg .u64 t; cvta.to.shared.u64 t, %1; cvt.u32.u64 %0, t; }" : "=r"(a) : "l"(p));
    return a;
}
__device__ __forceinline__ void cpa16(uint32_t s, const void* g) {
    asm volatile("cp.async.cg.shared.global [%0], [%1], 16;" :: "r"(s), "l"(g));
}
__device__ __forceinline__ void ldsm4(uint32_t (&d)[4], uint32_t addr) {
    asm volatile("ldmatrix.sync.aligned.m8n8.x4.shared.b16 {%0,%1,%2,%3}, [%4];"
                 : "=r"(d[0]), "=r"(d[1]), "=r"(d[2]), "=r"(d[3]) : "r"(addr));
}
__device__ __forceinline__ void mma16816(float (&d)[4], const uint32_t (&a)[4],
                                         uint32_t b0, uint32_t b1) {
    asm volatile("mma.sync.aligned.m16n8k16.row.col.f32.f16.f16.f32 "
                 "{%0,%1,%2,%3},{%4,%5,%6,%7},{%8,%9},{%0,%1,%2,%3};"
                 : "+f"(d[0]), "+f"(d[1]), "+f"(d[2]), "+f"(d[3])
                 : "r"(a[0]), "r"(a[1]), "r"(a[2]), "r"(a[3]), "r"(b0), "r"(b1));
}

// ===================== setup kernels =====================
__global__ void zero_kernel(float* p, int n) {
    for (int i = blockIdx.x * blockDim.x + threadIdx.x; i < n; i += gridDim.x * blockDim.x)
        p[i] = 0.f;
}

// Gate-interleaved fp16 weights: dest row nd = 4*ch + gate; source row = gate*1024 + ch.
__global__ void cat_half(__half* __restrict__ D,
                         const float* __restrict__ S1, int k1,
                         const float* __restrict__ S2, int k2, int Kp) {
    long total = (long)GG * Kp;
    for (long idx = blockIdx.x * (long)blockDim.x + threadIdx.x; idx < total;
         idx += (long)gridDim.x * blockDim.x) {
        int nd = (int)(idx / Kp);
        int k  = (int)(idx % Kp);
        int ch = nd >> 2, gate = nd & 3;
        int n = gate * HH + ch;
        float v = 0.f;
        if (k < k1) v = S1[(size_t)n * k1 + k];
        else if (k < k1 + k2) v = S2[(size_t)n * k2 + (k - k1)];
        D[idx] = __float2half(v);
    }
}

__global__ void transp_fc(const float* __restrict__ fcW) {
    int idx = blockIdx.x * blockDim.x + threadIdx.x;
    if (idx >= HH * OUTN) return;
    int k = idx >> 7, n = idx & 127;
    g_fcWT[idx] = fcW[(size_t)n * HH + k];
}

__global__ void bias_kernel(const float* eb0a, const float* eb0b,
                            const float* eb1a, const float* eb1b,
                            const float* db0a, const float* db0b,
                            const float* db1a, const float* db1b) {
    int nd = blockIdx.x * blockDim.x + threadIdx.x;
    if (nd >= GG) return;
    int ch = nd >> 2, gate = nd & 3;
    int n = gate * HH + ch;
    g_bias[0 * GG + nd] = eb0a[n] + eb0b[n];
    g_bias[1 * GG + nd] = eb1a[n] + eb1b[n];
    g_bias[2 * GG + nd] = db0a[n] + db0b[n];
    g_bias[3 * GG + nd] = db1a[n] + db1b[n];
}

// copy x_t (512 x 129) into staged enc A buffer (fp16)
__global__ void stage_x(const float* __restrict__ x, int t) {
    int idx = blockIdx.x * blockDim.x + threadIdx.x;
    if (idx >= BB * DD) return;
    int b = idx / DD, k = idx % DD;
    g_A[(size_t)b * KE0 + k] = __float2half(x[(size_t)b * (TT * DD) + t * DD + k]);
}

// ===================== fused GEMM + LSTM cell =====================
// gates[m][nd] = sum_k A(m,k)*W(nd,k) + bias[nd], nd = 4*ch+gate (interleaved).
// fp16 operands, fp32 accumulate; cell applied in epilogue.
// CTA 128x128, 8 warps (2m x 4n), K-chunk 64, 3-stage cp.async, XOR swizzle.
#define TBYTES 16384                 // 128 rows x 128B
#define STAGE_B (2 * TBYTES)         // 32768 (A tile + W tile)
#define SMEM_SZ (3 * STAGE_B)        // 98304; epilogue reuses 128*132*4 = 67584

__global__ __launch_bounds__(256, 1)
void gemm_cell(const __half* __restrict__ Ag, int lda,
               const __half* __restrict__ Wg, int ldw,
               const float* __restrict__ bias,
               float* __restrict__ Cc,            // cell state [BB][HH]
               const int* __restrict__ lengths, int t, int use_mask, int hoff,
               __half* __restrict__ sA,           // optional staging (enc L0 h0), else null
               int K) {
    extern __shared__ char smem[];
    const uint32_t sb = smem_u32(smem);
    const int tid = threadIdx.x;
    const int l = tid & 31;
    const int wid = tid >> 5;
    const int warp_m = wid >> 2;          // 0..1
    const int warp_n = wid & 3;           // 0..3
    const int m0 = blockIdx.y * 128;
    const int n0 = blockIdx.x * 128;

    // ---- loader mapping: thread -> (rowL + 32*it, col16), XOR swizzle ----
    const int rowL = tid >> 3;            // 0..31
    const int colL = tid & 7;             // 16B column
    const uint32_t swL = (uint32_t)(colL ^ (rowL & 7)) * 16;
    const size_t ldaB = (size_t)lda * 2, ldwB = (size_t)ldw * 2;
    const char* pA = (const char*)Ag + (size_t)(m0 + rowL) * ldaB + colL * 16;
    const char* pW = (const char*)Wg + (size_t)(n0 + rowL) * ldwB + colL * 16;
    const int nchunks = K >> 6;

#define LOADCHUNK(s, kc) do {                                                      \
    const uint32_t st_ = sb + (s) * STAGE_B;                                       \
    const size_t ko_ = (size_t)(kc) * 128;                                         \
    _Pragma("unroll")                                                              \
    for (int it = 0; it < 4; it++) {                                               \
        const uint32_t so_ = (uint32_t)(rowL + 32 * it) * 128 + swL;               \
        cpa16(st_ + 0 * TBYTES + so_, pA + ko_ + (size_t)(32 * it) * ldaB);        \
        cpa16(st_ + 1 * TBYTES + so_, pW + ko_ + (size_t)(32 * it) * ldwB);        \
    }                                                                              \
    asm volatile("cp.async.commit_group;");                                        \
} while (0)

    // ---- ldmatrix lane bases ----
    uint32_t arow[4], ar7[4];
#pragma unroll
    for (int wm = 0; wm < 4; wm++) {
        const uint32_t r = warp_m * 64 + wm * 16 + (l & 15);
        arow[wm] = r * 128;
        ar7[wm]  = r & 7;
    }
    uint32_t brow[2], br7[2];
#pragma unroll
    for (int p = 0; p < 2; p++) {
        const uint32_t r = warp_n * 32 + p * 16 + ((l >> 4) << 3) + (l & 7);
        brow[p] = r * 128;
        br7[p]  = r & 7;
    }
    const uint32_t acsel = (uint32_t)(l >> 4);       // A: k8 half select
    const uint32_t bcsel = (uint32_t)((l >> 3) & 1); // B: k8 half select

    float acc[4][4][4];
#pragma unroll
    for (int i = 0; i < 4; i++)
#pragma unroll
        for (int j = 0; j < 4; j++)
#pragma unroll
            for (int q = 0; q < 4; q++) acc[i][j][q] = 0.f;

    // ---- preload chunks 0,1 ----
    LOADCHUNK(0, 0);
    LOADCHUNK(1, 1);

    for (int kc = 0; kc < nchunks; kc++) {
        if (kc + 2 < nchunks) {
            asm volatile("cp.async.wait_group 1;");
        } else {
            asm volatile("cp.async.wait_group 0;");
        }
        __syncthreads();
        if (kc + 2 < nchunks) {
            const int s = (kc + 2) % 3;
            LOADCHUNK(s, kc + 2);
        }
        const uint32_t st = sb + (kc % 3) * STAGE_B;
#pragma unroll
        for (int ks = 0; ks < 4; ks++) {
            uint32_t AH[4][4], BH[2][4];
#pragma unroll
            for (int wm = 0; wm < 4; wm++) {
                const uint32_t c = (uint32_t)(2 * ks) + acsel;
                const uint32_t off = arow[wm] + ((c ^ ar7[wm]) << 4);
                ldsm4(AH[wm], st + 0 * TBYTES + off);
            }
#pragma unroll
            for (int p = 0; p < 2; p++) {
                const uint32_t c = (uint32_t)(2 * ks) + bcsel;
                const uint32_t off = brow[p] + ((c ^ br7[p]) << 4);
                ldsm4(BH[p], st + 1 * TBYTES + off);
            }
#pragma unroll
            for (int wm = 0; wm < 4; wm++) {
#pragma unroll
                for (int wn = 0; wn < 4; wn++) {
                    const int p = wn >> 1, h = (wn & 1) << 1;
                    mma16816(acc[wm][wn], AH[wm], BH[p][h], BH[p][h + 1]);
                }
            }
        }
        __syncthreads();
    }

    // ---- epilogue: acc + bias -> smem (row stride 132 floats) ----
    float* cs = (float*)smem;
#pragma unroll
    for (int wn = 0; wn < 4; wn++) {
        const int cl = warp_n * 32 + wn * 8 + (l & 3) * 2;
        const float2 bv = *(const float2*)(bias + n0 + cl);
#pragma unroll
        for (int wm = 0; wm < 4; wm++) {
            const int rl = warp_m * 64 + wm * 16 + (l >> 2);
            cs[rl * 132 + cl]           = acc[wm][wn][0] + bv.x;
            cs[rl * 132 + cl + 1]       = acc[wm][wn][1] + bv.y;
            cs[(rl + 8) * 132 + cl]     = acc[wm][wn][2] + bv.x;
            cs[(rl + 8) * 132 + cl + 1] = acc[wm][wn][3] + bv.y;
        }
    }
    __syncthreads();

    // ---- LSTM cell: 128 batch x 32 channels, 16 per thread ----
    const int ch0 = n0 >> 2;
#pragma unroll
    for (int it = 0; it < 16; it++) {
        const int idx = it * 256 + tid;
        const int bl = idx >> 5;
        const int jl = idx & 31;
        const float4 v = *(const float4*)&cs[bl * 132 + 4 * jl];
        const int b = m0 + bl;
        const int j = ch0 + jl;
        const float ig = 1.f / (1.f + __expf(-v.x));
        const float fg = 1.f / (1.f + __expf(-v.y));
        const float gg = tanhf(v.z);
        const float og = 1.f / (1.f + __expf(-v.w));
        const size_t cidx = (size_t)b * HH + j;
        const size_t hidx = (size_t)b * XS + hoff + j;
        const float cold = Cc[cidx];
        float cn = fg * cold + ig * gg;
        float hn = og * tanhf(cn);
        if (use_mask && t >= lengths[b]) {
            cn = cold;
            hn = g_X[hidx];
        }
        Cc[cidx] = cn;
        g_X[hidx] = hn;
        const __half hh = __float2half(hn);
        g_Xh[hidx] = hh;
        if (sA) {
            sA[(size_t)b * KE0 + DD + j] = hh;
        }
    }
}

// ===================== fc: out = h1 @ fcW^T + b; writes next xt =====================
__global__ void fc_kernel(const float* __restrict__ fcb,
                          float* __restrict__ out, int t) {
    __shared__ float red[2][4][128];
    const int tid = threadIdx.x;
    const int n = tid & 127;
    const int half = tid >> 7;
    const int b0 = blockIdx.x * 4;
    const float* h1p = g_X + (size_t)b0 * XS + 1152;
    float a0 = 0.f, a1 = 0.f, a2 = 0.f, a3 = 0.f;
    const int kb = half * 512;
#pragma unroll 4
    for (int k = kb; k < kb + 512; k++) {
        const float w = g_fcWT[k * OUTN + n];
        a0 += h1p[k] * w;
        a1 += h1p[XS + k] * w;
        a2 += h1p[2 * XS + k] * w;
        a3 += h1p[3 * XS + k] * w;
    }
    red[half][0][n] = a0; red[half][1][n] = a1;
    red[half][2][n] = a2; red[half][3][n] = a3;
    __syncthreads();
    if (half == 0) {
#pragma unroll
        for (int i = 0; i < 4; i++) {
            const float v = red[0][i][n] + red[1][i][n] + fcb[n];
            out[((size_t)(b0 + i) * STEPS + t) * OUTN + n] = v;
            g_Xh[(size_t)(b0 + i) * XS + n] = __float2half(v);
        }
    }
}

// ===================== host =====================
extern "C" void kernel_launch(void* const* d_in, const int* in_sizes, int n_in,
                              void* d_out, int out_size) {
    const float* x     = (const float*)d_in[0];
    const int*   lens  = (const int*)  d_in[1];
    const float* eWih0 = (const float*)d_in[2];
    const float* eWhh0 = (const float*)d_in[3];
    const float* ebih0 = (const float*)d_in[4];
    const float* ebhh0 = (const float*)d_in[5];
    const float* eWih1 = (const float*)d_in[6];
    const float* eWhh1 = (const float*)d_in[7];
    const float* ebih1 = (const float*)d_in[8];
    const float* ebhh1 = (const float*)d_in[9];
    const float* dWih0 = (const float*)d_in[10];
    const float* dWhh0 = (const float*)d_in[11];
    const float* dbih0 = (const float*)d_in[12];
    const float* dbhh0 = (const float*)d_in[13];
    const float* dWih1 = (const float*)d_in[14];
    const float* dWhh1 = (const float*)d_in[15];
    const float* dbih1 = (const float*)d_in[16];
    const float* dbhh1 = (const float*)d_in[17];
    const float* fcW   = (const float*)d_in[18];
    const float* fcb   = (const float*)d_in[19];
    float* out = (float*)d_out;

    float *X, *C0, *C1, *Bias;
    __half *Xh, *A, *We0, *We1, *Wd0, *Wd1;
    cudaGetSymbolAddress((void**)&X,    g_X);
    cudaGetSymbolAddress((void**)&C0,   g_C0);
    cudaGetSymbolAddress((void**)&C1,   g_C1);
    cudaGetSymbolAddress((void**)&Bias, g_bias);
    cudaGetSymbolAddress((void**)&Xh,   g_Xh);
    cudaGetSymbolAddress((void**)&A,    g_A);
    cudaGetSymbolAddress((void**)&We0,  g_We0);
    cudaGetSymbolAddress((void**)&We1,  g_We1);
    cudaGetSymbolAddress((void**)&Wd0,  g_Wd0);
    cudaGetSymbolAddress((void**)&Wd1,  g_Wd1);

    cudaFuncSetAttribute(gemm_cell, cudaFuncAttributeMaxDynamicSharedMemorySize, SMEM_SZ);

    // ---- setup ----
    zero_kernel<<<2048, 256>>>(X,  BB * XS);
    zero_kernel<<<2048, 256>>>(C0, BB * HH);
    zero_kernel<<<2048, 256>>>(C1, BB * HH);
    zero_kernel<<<2048, 256>>>((float*)Xh, BB * XS / 2);
    zero_kernel<<<2048, 256>>>((float*)A,  BB * KE0 / 2);
    bias_kernel<<<(GG + 255) / 256, 256>>>(ebih0, ebhh0, ebih1, ebhh1,
                                           dbih0, dbhh0, dbih1, dbhh1);
    cat_half<<<4096, 256>>>(We0, eWih0, DD,   eWhh0, HH, KE0);
    cat_half<<<4096, 256>>>(We1, eWih1, HH,   eWhh1, HH, KE1);
    cat_half<<<4096, 256>>>(Wd0, dWih0, OUTN, dWhh0, HH, KD0);
    cat_half<<<4096, 256>>>(Wd1, dWih1, HH,   dWhh1, HH, KD1);
    transp_fc<<<(HH * OUTN + 255) / 256, 256>>>(fcW);

    const dim3 gg(32, 4), gb(256);

    // ---- encoder: 82 steps ----
    for (int t = 0; t < TT; t++) {
        stage_x<<<(BB * DD + 255) / 256, 256>>>(x, t);
        gemm_cell<<<gg, gb, SMEM_SZ>>>(A, KE0, We0, KE0,
                                       Bias + 0 * GG, C0, lens, t, 1, 128,
                                       A, KE0);
        gemm_cell<<<gg, gb, SMEM_SZ>>>(Xh + 128, XS, We1, KE1,
                                       Bias + 1 * GG, C1, lens, t, 1, 1152,
                                       nullptr, KE1);
    }

    // ---- decoder: 100 steps ----
    for (int t = 0; t < STEPS; t++) {
        gemm_cell<<<gg, gb, SMEM_SZ>>>(Xh, XS, Wd0, KD0,
                                       Bias + 2 * GG, C0, lens, t, 0, 128,
                                       nullptr, KD0);
        gemm_cell<<<gg, gb, SMEM_SZ>>>(Xh + 128, XS, Wd1, KD1,
                                       Bias + 3 * GG, C1, lens, t, 0, 1152,
                                       nullptr, KD1);
        fc_kernel<<<128, 256>>>(fcb, out, t);
    }
}